// round 2
// baseline (speedup 1.0000x reference)
#include <cuda_runtime.h>
#include <math.h>
#include <stdint.h>

// ---------------- problem constants ----------------
constexpr int cB = 4, cT = 4096, cD = 1024, cH = 8;
constexpr int cDK = 1024, cDV = 2048, cDKH = 128, cDVH = 256;
constexpr int cRANK = 16, cLOOPD = 128, cNL = 4;
constexpr int cCH = 64;                 // GLA chunk length
constexpr int cNC = cT / cCH;           // 64 chunks
constexpr int cBH = cB * cH;            // 32
constexpr int cM = cB * cT;             // 16384 rows

// ---------------- device scratch (static: no allocation allowed) ----------------
__device__ float g_h[cM * cD];
__device__ float g_x[cM * cD];
__device__ float g_q[cM * cDK];
__device__ float g_k[cM * cDK];
__device__ float g_la[cM * cDK];
__device__ float g_v[cM * cDV];
__device__ float g_gate[cM * cDV];
__device__ float g_o[cM * cDV];
__device__ float g_kv[cNC * cBH * cDKH * cDVH];   // per-chunk K'^T V
__device__ float g_S[cNC * cBH * cDKH * cDVH];    // state snapshots
__device__ float g_bdec[cNC * cBH * cDKH];
__device__ float g_gla[cM * cD];
__device__ float g_lora[cM * cRANK];
__device__ float g_hnew[cM * cD];
__device__ float g_hout[cM * cD];
__device__ float g_cum[cM];
__device__ float g_halt[cM];
__device__ float g_iat[cD * cD];
__device__ float g_ibt[cD * cD];

// ---------------- utility kernels ----------------
__global__ void k_copy(float* __restrict__ dst, const float* __restrict__ src) {
    int idx = blockIdx.x * 256 + threadIdx.x;
    dst[idx] = src[idx];
}
__global__ void k_zero(float* __restrict__ dst) {
    int idx = blockIdx.x * 256 + threadIdx.x;
    dst[idx] = 0.f;
}
__global__ void k_zero_state(float* __restrict__ cum, float* __restrict__ halt) {
    int idx = blockIdx.x * 256 + threadIdx.x;
    cum[idx] = 0.f; halt[idx] = 0.f;
}
__global__ void k_transpose(const float* __restrict__ in, float* __restrict__ out) {
    int idx = blockIdx.x * 256 + threadIdx.x;      // over D*D
    int i = idx >> 10, j = idx & 1023;
    out[(size_t)j * cD + i] = in[idx];
}

// ---------------- fused add-loop-embed + rmsnorm(h+e) ----------------
__global__ void __launch_bounds__(256) k_prep(float* __restrict__ h, const float* __restrict__ e,
                                              const float* __restrict__ nw, const float* __restrict__ ltab,
                                              float* __restrict__ x) {
    int row = blockIdx.x; size_t base = (size_t)row * cD;
    int tid = threadIdx.x;
    if (tid < cLOOPD) h[base + tid] += ltab[tid];
    __syncthreads();
    float vals[4]; float ss = 0.f;
#pragma unroll
    for (int i = 0; i < 4; i++) {
        int c = tid + i * 256;
        float v = h[base + c] + e[base + c];
        vals[i] = v; ss += v * v;
    }
    __shared__ float red[256];
    red[tid] = ss; __syncthreads();
    for (int s = 128; s > 0; s >>= 1) { if (tid < s) red[tid] += red[tid + s]; __syncthreads(); }
    float rs = rsqrtf(red[0] * (1.f / cD) + 1e-6f);
#pragma unroll
    for (int i = 0; i < 4; i++) {
        int c = tid + i * 256;
        x[base + c] = vals[i] * rs * nw[c];
    }
}

// ---------------- final rmsnorm ----------------
__global__ void __launch_bounds__(256) k_rmsnorm(const float* __restrict__ in, const float* __restrict__ nw,
                                                 float* __restrict__ out) {
    int row = blockIdx.x; size_t base = (size_t)row * cD;
    int tid = threadIdx.x;
    float vals[4]; float ss = 0.f;
#pragma unroll
    for (int i = 0; i < 4; i++) {
        int c = tid + i * 256;
        float v = in[base + c];
        vals[i] = v; ss += v * v;
    }
    __shared__ float red[256];
    red[tid] = ss; __syncthreads();
    for (int s = 128; s > 0; s >>= 1) { if (tid < s) red[tid] += red[tid + s]; __syncthreads(); }
    float rs = rsqrtf(red[0] * (1.f / cD) + 1e-6f);
#pragma unroll
    for (int i = 0; i < 4; i++) {
        int c = tid + i * 256;
        out[base + c] = vals[i] * rs * nw[c];
    }
}

// ---------------- generic fp32 SGEMM: C = epi(A(*Amul) @ B + Cinit) ----------------
// epi: 0 none, 1 scale, 2 logsigmoid/16, 3 silu
__global__ void __launch_bounds__(256) gemm_k(const float* __restrict__ A, const float* __restrict__ Bm,
                                              float* __restrict__ C, const float* __restrict__ Cinit,
                                              const float* __restrict__ Amul,
                                              int M, int N, int K, float scale, int epi) {
    __shared__ float As[16][128];
    __shared__ float Bs[16][128];
    int tid = threadIdx.x;
    int m0 = blockIdx.y * 128, n0 = blockIdx.x * 128;
    float acc[8][8];
#pragma unroll
    for (int i = 0; i < 8; i++)
#pragma unroll
        for (int j = 0; j < 8; j++) acc[i][j] = 0.f;
    int tm = (tid >> 4) << 3, tn = (tid & 15) << 3;

    for (int k0 = 0; k0 < K; k0 += 16) {
#pragma unroll
        for (int l = 0; l < 2; l++) {
            int idx = tid + l * 256;          // 0..511
            int row = idx >> 2;
            int cl = (idx & 3) * 4;
            float4 av = *(const float4*)&A[(size_t)(m0 + row) * K + k0 + cl];
            if (Amul) {
                float4 mv = *(const float4*)&Amul[(size_t)(m0 + row) * K + k0 + cl];
                av.x *= mv.x; av.y *= mv.y; av.z *= mv.z; av.w *= mv.w;
            }
            As[cl + 0][row] = av.x; As[cl + 1][row] = av.y;
            As[cl + 2][row] = av.z; As[cl + 3][row] = av.w;
        }
#pragma unroll
        for (int l = 0; l < 2; l++) {
            int idx = tid + l * 256;
            int kr = idx >> 5;
            int nc = (idx & 31) * 4;
            *(float4*)&Bs[kr][nc] = *(const float4*)&Bm[(size_t)(k0 + kr) * N + n0 + nc];
        }
        __syncthreads();
#pragma unroll
        for (int kk = 0; kk < 16; kk++) {
            float a[8], b[8];
            *(float4*)&a[0] = *(float4*)&As[kk][tm];
            *(float4*)&a[4] = *(float4*)&As[kk][tm + 4];
            *(float4*)&b[0] = *(float4*)&Bs[kk][tn];
            *(float4*)&b[4] = *(float4*)&Bs[kk][tn + 4];
#pragma unroll
            for (int i = 0; i < 8; i++)
#pragma unroll
                for (int j = 0; j < 8; j++) acc[i][j] += a[i] * b[j];
        }
        __syncthreads();
    }
    const float inv16 = 0.0625f;
#pragma unroll
    for (int i = 0; i < 8; i++) {
        size_t rowoff = (size_t)(m0 + tm + i) * N + n0 + tn;
#pragma unroll
        for (int j = 0; j < 8; j++) {
            float v = acc[i][j];
            if (Cinit) v += Cinit[rowoff + j];
            if (epi == 1) v *= scale;
            else if (epi == 2) v = (fminf(v, 0.f) - log1pf(expf(-fabsf(v)))) * inv16;
            else if (epi == 3) v = v / (1.f + expf(-v));
            C[rowoff + j] = v;
        }
    }
}

// ---------------- GLA chunk kernel: cumsum decay, intra attn, chunk KV ----------------
// smem floats: cum 8192 | qt 8192 | kt 8448(pad 132) | kc 8192 | v 16384  = 49408
constexpr int SMEM_CHUNK = 49408 * 4;
__global__ void __launch_bounds__(256) k_chunk(float* __restrict__ pq, const float* __restrict__ pk,
                                               const float* __restrict__ pla, const float* __restrict__ pv,
                                               float* __restrict__ po, float* __restrict__ pkv,
                                               float* __restrict__ pbdec) {
    extern __shared__ float sm[];
    float* s_cum = sm;
    float* s_qt = sm + 8192;
    float* s_kt = sm + 16384;     // stride 132
    float* s_kc = sm + 24832;
    float* s_v  = sm + 33024;
    float* s_A  = sm;             // aliases cum (dead after phase A)

    int cidx = blockIdx.x;
    int c = cidx / cBH, bh = cidx - c * cBH;
    int b = bh >> 3, hh = bh & 7;
    int t0 = c * cCH;
    size_t qbase = ((size_t)b * cT + t0) * cDK + hh * cDKH;
    size_t vbase = ((size_t)b * cT + t0) * cDV + hh * cDVH;
    int tid = threadIdx.x;

    if (tid < 128) {
        int d = tid;
        float cum = 0.f;
        for (int i = 0; i < cCH; i++) {
            size_t off = qbase + (size_t)i * cDK + d;
            cum += pla[off];
            s_cum[i * 128 + d] = cum;
            s_qt[i * 128 + d] = pq[off] * expf(cum);
            s_kt[i * 132 + d] = pk[off] * expf(-cum);
            s_kc[i * 128 + d] = pk[off];
        }
        float latot = cum;
        pbdec[(size_t)cidx * cDKH + d] = expf(latot);
        for (int i = 0; i < cCH; i++)
            s_kc[i * 128 + d] *= expf(latot - s_cum[i * 128 + d]);
        for (int i = 0; i < cCH; i++)
            pq[qbase + (size_t)i * cDK + d] = s_qt[i * 128 + d];   // q~ for inter pass
    } else {
        int lt = tid - 128;
        for (int l = 0; l < 32; l++) {
            int idx4 = lt + l * 128;           // 0..4095 float4s
            int i = idx4 >> 6;
            int u4 = (idx4 & 63) * 4;
            *(float4*)&s_v[i * 256 + u4] = *(const float4*)&pv[vbase + (size_t)i * cDV + u4];
        }
    }
    __syncthreads();

    // A = mask(q~ k~^T)
    for (int idx = tid; idx < cCH * cCH; idx += 256) {
        int i = idx >> 6, j = idx & 63;
        float sum = 0.f;
        if (j <= i) {
            const float* qp = &s_qt[i * 128];
            const float* kp = &s_kt[j * 132];
#pragma unroll
            for (int d = 0; d < 128; d += 4) {
                float4 qa = *(const float4*)&qp[d];
                float4 kb = *(const float4*)&kp[d];
                sum += qa.x * kb.x + qa.y * kb.y + qa.z * kb.z + qa.w * kb.w;
            }
        }
        s_A[idx] = sum;
    }
    __syncthreads();

    // O_intra = A @ V
    for (int idx = tid; idx < cCH * cDVH; idx += 256) {
        int i = idx >> 8, u = idx & 255;
        float sum = 0.f;
        for (int j = 0; j <= i; j++) sum += s_A[i * 64 + j] * s_v[j * 256 + u];
        po[vbase + (size_t)i * cDV + u] = sum;
    }

    // KV_c = kc^T @ V
    for (int idx = tid; idx < cDKH * cDVH; idx += 256) {
        int d = idx >> 8, u = idx & 255;
        float sum = 0.f;
#pragma unroll 8
        for (int i = 0; i < cCH; i++) sum += s_kc[i * 128 + d] * s_v[i * 256 + u];
        pkv[(size_t)cidx * (cDKH * cDVH) + idx] = sum;
    }
}

// ---------------- sequential state propagation (64 light steps) ----------------
__global__ void __launch_bounds__(256) k_state(const float* __restrict__ pkv, const float* __restrict__ pbdec,
                                               float* __restrict__ Sout) {
    int blk = blockIdx.x;                // BH*8
    int bh = blk >> 3;
    int vs = (blk & 7) * 32;
    int tid = threadIdx.x;
    int kr = tid >> 1;
    int vofs = vs + (tid & 1) * 16;
    float S[16];
#pragma unroll
    for (int j = 0; j < 16; j++) S[j] = 0.f;
    for (int c = 0; c < cNC; c++) {
        size_t base = ((size_t)c * cBH + bh) * (cDKH * cDVH) + (size_t)kr * cDVH + vofs;
        float bd = pbdec[((size_t)c * cBH + bh) * cDKH + kr];
#pragma unroll
        for (int j = 0; j < 16; j += 4) {
            *(float4*)&Sout[base + j] = make_float4(S[j], S[j + 1], S[j + 2], S[j + 3]); // snapshot BEFORE update
            float4 kvv = *(const float4*)&pkv[base + j];
            S[j]     = bd * S[j]     + kvv.x;
            S[j + 1] = bd * S[j + 1] + kvv.y;
            S[j + 2] = bd * S[j + 2] + kvv.z;
            S[j + 3] = bd * S[j + 3] + kvv.w;
        }
    }
}

// ---------------- inter-chunk output: O += q~ @ S_c ----------------
__global__ void __launch_bounds__(256) k_inter(const float* __restrict__ pq, const float* __restrict__ S,
                                               float* __restrict__ po) {
    __shared__ float s_q[cCH * cDKH];    // 32KB
    int cidx = blockIdx.x;
    int c = cidx / cBH, bh = cidx - c * cBH;
    int b = bh >> 3, hh = bh & 7;
    int t0 = c * cCH;
    size_t qbase = ((size_t)b * cT + t0) * cDK + hh * cDKH;
    size_t vbase = ((size_t)b * cT + t0) * cDV + hh * cDVH;
    int tid = threadIdx.x;
#pragma unroll
    for (int l = 0; l < 8; l++) {
        int idx4 = tid + l * 256;         // 0..2047
        int i = idx4 >> 5;
        int d4 = (idx4 & 31) * 4;
        *(float4*)&s_q[i * 128 + d4] = *(const float4*)&pq[qbase + (size_t)i * cDK + d4];
    }
    __syncthreads();
    int u = tid;
    float acc[cCH];
#pragma unroll
    for (int i = 0; i < cCH; i++) acc[i] = 0.f;
    size_t sbase = (size_t)cidx * (cDKH * cDVH) + u;
    for (int d = 0; d < cDKH; d += 4) {
        float sv0 = S[sbase + (size_t)(d + 0) * cDVH];
        float sv1 = S[sbase + (size_t)(d + 1) * cDVH];
        float sv2 = S[sbase + (size_t)(d + 2) * cDVH];
        float sv3 = S[sbase + (size_t)(d + 3) * cDVH];
#pragma unroll
        for (int i = 0; i < cCH; i++) {
            float4 qv = *(const float4*)&s_q[i * 128 + d];
            acc[i] += qv.x * sv0 + qv.y * sv1 + qv.z * sv2 + qv.w * sv3;
        }
    }
#pragma unroll
    for (int i = 0; i < cCH; i++) {
        size_t off = vbase + (size_t)i * cDV + u;
        po[off] += acc[i];
    }
}

// ---------------- LoRA ----------------
__global__ void __launch_bounds__(256) k_lora_down(const float* __restrict__ g, const float* __restrict__ A,
                                                   float* __restrict__ out) {
    int warp = threadIdx.x >> 5, lane = threadIdx.x & 31;
    int m = blockIdx.x * 8 + warp;
    const float* grow = &g[(size_t)m * cD];
    float acc[cRANK];
#pragma unroll
    for (int r = 0; r < cRANK; r++) acc[r] = 0.f;
    for (int kk = lane; kk < cD; kk += 32) {
        float a = grow[kk];
        const float4* Ap = (const float4*)&A[(size_t)kk * cRANK];
        float4 b0 = Ap[0], b1 = Ap[1], b2 = Ap[2], b3 = Ap[3];
        acc[0] += a * b0.x; acc[1] += a * b0.y; acc[2] += a * b0.z; acc[3] += a * b0.w;
        acc[4] += a * b1.x; acc[5] += a * b1.y; acc[6] += a * b1.z; acc[7] += a * b1.w;
        acc[8] += a * b2.x; acc[9] += a * b2.y; acc[10] += a * b2.z; acc[11] += a * b2.w;
        acc[12] += a * b3.x; acc[13] += a * b3.y; acc[14] += a * b3.z; acc[15] += a * b3.w;
    }
#pragma unroll
    for (int r = 0; r < cRANK; r++)
        for (int s = 16; s > 0; s >>= 1) acc[r] += __shfl_xor_sync(0xffffffffu, acc[r], s);
    if (lane == 0) {
#pragma unroll
        for (int r = 0; r < cRANK; r++) out[(size_t)m * cRANK + r] = acc[r];
    }
}
__global__ void __launch_bounds__(256) k_lora_up(const float* __restrict__ tmp, const float* __restrict__ Bm,
                                                 float* __restrict__ g) {
    int idx = blockIdx.x * 256 + threadIdx.x;
    int m = idx >> 10, n = idx & 1023;
    const float* tr = &tmp[(size_t)m * cRANK];
    float s = 0.f;
#pragma unroll
    for (int r = 0; r < cRANK; r++) s += tr[r] * Bm[r * cD + n];
    g[idx] += s;
}

// ---------------- ACT halting + state carry ----------------
__global__ void __launch_bounds__(256) k_act(const float* __restrict__ hnew, const float* __restrict__ act_w,
                                             const float* __restrict__ act_b, float* __restrict__ h,
                                             float* __restrict__ hout, float* __restrict__ cum,
                                             float* __restrict__ halt) {
    int row = blockIdx.x; size_t base = (size_t)row * cD;
    int tid = threadIdx.x;
    float ss = 0.f;
#pragma unroll
    for (int i = 0; i < 4; i++) {
        int c = tid + i * 256;
        ss += hnew[base + c] * act_w[c];
    }
    __shared__ float red[256]; __shared__ float wsh;
    red[tid] = ss; __syncthreads();
    for (int s = 128; s > 0; s >>= 1) { if (tid < s) red[tid] += red[tid + s]; __syncthreads(); }
    if (tid == 0) {
        float z = red[0] + act_b[0];
        float p = 1.f / (1.f + expf(-z));
        float cm = cum[row]; float hl = halt[row];
        float p_eff = (hl > 0.5f) ? 0.f : p;
        float ncum = cm + p_eff;
        bool newly = (hl < 0.5f) && (ncum >= 0.99f);
        float w = newly ? (1.f - cm) : p_eff;
        cum[row] = ncum;
        if (newly) halt[row] = 1.f;
        wsh = w;
    }
    __syncthreads();
    float w = wsh;
#pragma unroll
    for (int i = 0; i < 4; i++) {
        int c = tid + i * 256;
        float v = hnew[base + c];
        hout[base + c] += w * v;
        h[base + c] = v;
    }
}

// ---------------- host ----------------
static void gemm(const float* A, const float* Bm, float* C, const float* Cinit, const float* Amul,
                 int M, int N, int K, float scale, int epi) {
    dim3 g(N / 128, M / 128);
    gemm_k<<<g, 256>>>(A, Bm, C, Cinit, Amul, M, N, K, scale, epi);
}

extern "C" void kernel_launch(void* const* d_in, const int* in_sizes, int n_in,
                              void* d_out, int out_size) {
    const float* in_h  = (const float*)d_in[0];
    const float* in_e  = (const float*)d_in[1];
    const float* nw    = (const float*)d_in[2];
    const float* onw   = (const float*)d_in[3];
    const float* Wq    = (const float*)d_in[4];
    const float* Wk    = (const float*)d_in[5];
    const float* Wv    = (const float*)d_in[6];
    const float* Wgk   = (const float*)d_in[7];
    const float* Wg    = (const float*)d_in[8];
    const float* Wo    = (const float*)d_in[9];
    const float* loraA = (const float*)d_in[10];
    const float* loraB = (const float*)d_in[11];
    const float* injA  = (const float*)d_in[12];
    const float* injB  = (const float*)d_in[13];
    const float* act_w = (const float*)d_in[14];
    const float* act_b = (const float*)d_in[15];
    const float* ltab  = (const float*)d_in[16];
    float* out = (float*)d_out;

    float *p_h, *p_x, *p_q, *p_k, *p_la, *p_v, *p_gate, *p_o, *p_kv, *p_S, *p_bdec,
          *p_gla, *p_lora, *p_hnew, *p_hout, *p_cum, *p_halt, *p_iat, *p_ibt;
    cudaGetSymbolAddress((void**)&p_h, g_h);
    cudaGetSymbolAddress((void**)&p_x, g_x);
    cudaGetSymbolAddress((void**)&p_q, g_q);
    cudaGetSymbolAddress((void**)&p_k, g_k);
    cudaGetSymbolAddress((void**)&p_la, g_la);
    cudaGetSymbolAddress((void**)&p_v, g_v);
    cudaGetSymbolAddress((void**)&p_gate, g_gate);
    cudaGetSymbolAddress((void**)&p_o, g_o);
    cudaGetSymbolAddress((void**)&p_kv, g_kv);
    cudaGetSymbolAddress((void**)&p_S, g_S);
    cudaGetSymbolAddress((void**)&p_bdec, g_bdec);
    cudaGetSymbolAddress((void**)&p_gla, g_gla);
    cudaGetSymbolAddress((void**)&p_lora, g_lora);
    cudaGetSymbolAddress((void**)&p_hnew, g_hnew);
    cudaGetSymbolAddress((void**)&p_hout, g_hout);
    cudaGetSymbolAddress((void**)&p_cum, g_cum);
    cudaGetSymbolAddress((void**)&p_halt, g_halt);
    cudaGetSymbolAddress((void**)&p_iat, g_iat);
    cudaGetSymbolAddress((void**)&p_ibt, g_ibt);

    cudaFuncSetAttribute(k_chunk, cudaFuncAttributeMaxDynamicSharedMemorySize, SMEM_CHUNK);

    const int nBig = cM * cD / 256;       // 65536 blocks
    k_copy<<<nBig, 256>>>(p_h, in_h);
    k_zero<<<nBig, 256>>>(p_hout);
    k_zero_state<<<cM / 256, 256>>>(p_cum, p_halt);
    k_transpose<<<cD * cD / 256, 256>>>(injA, p_iat);
    k_transpose<<<cD * cD / 256, 256>>>(injB, p_ibt);

    const float qscale = 0.08838834764831845f;     // 128^-0.5

    for (int t = 0; t < cNL; t++) {
        k_prep<<<cM, 256>>>(p_h, in_e, nw, ltab + t * cLOOPD, p_x);
        gemm(p_x, Wq, p_q, nullptr, nullptr, cM, cDK, cD, qscale, 1);
        gemm(p_x, Wk, p_k, nullptr, nullptr, cM, cDK, cD, 0.f, 0);
        gemm(p_x, Wgk, p_la, nullptr, nullptr, cM, cDK, cD, 0.f, 2);
        gemm(p_x, Wv, p_v, nullptr, nullptr, cM, cDV, cD, 0.f, 0);
        gemm(p_x, Wg, p_gate, nullptr, nullptr, cM, cDV, cD, 0.f, 3);

        k_chunk<<<cNC * cBH, 256, SMEM_CHUNK>>>(p_q, p_k, p_la, p_v, p_o, p_kv, p_bdec);
        k_state<<<cBH * 8, 256>>>(p_kv, p_bdec, p_S);
        k_inter<<<cNC * cBH, 256>>>(p_q, p_S, p_o);

        gemm(p_o, Wo, p_gla, nullptr, p_gate, cM, cD, cDV, 0.f, 0);

        k_lora_down<<<cM / 8, 256>>>(p_gla, loraA + (size_t)t * cD * cRANK, p_lora);
        k_lora_up<<<nBig, 256>>>(p_lora, loraB + (size_t)t * cRANK * cD, p_gla);

        gemm(p_h, p_iat, p_hnew, p_gla, nullptr, cM, cD, cD, 0.f, 0);
        gemm(in_e, p_ibt, p_hnew, p_hnew, nullptr, cM, cD, cD, 0.f, 0);

        k_act<<<cM, 256>>>(p_hnew, act_w, act_b, p_h, p_hout, p_cum, p_halt);
    }
    k_rmsnorm<<<cM, 256>>>(p_hout, onw, out);
}

// round 6
// speedup vs baseline: 2.3884x; 2.3884x over previous
#include <cuda_runtime.h>
#include <cuda_bf16.h>
#include <math.h>
#include <stdint.h>

// ---------------- problem constants ----------------
constexpr int cB = 4, cT = 4096, cD = 1024, cH = 8;
constexpr int cDK = 1024, cDV = 2048, cDKH = 128, cDVH = 256;
constexpr int cRANK = 16, cLOOPD = 128, cNL = 4;
constexpr int cCH = 64;                 // GLA chunk length
constexpr int cNC = cT / cCH;           // 64 chunks
constexpr int cBH = cB * cH;            // 32
constexpr int cM = cB * cT;             // 16384 rows

// ---------------- device scratch ----------------
__device__ float g_h[cM * cD];
__device__ float g_q[cM * cDK];
__device__ float g_k[cM * cDK];
__device__ float g_la[cM * cDK];
__device__ float g_v[cM * cDV];
__device__ float g_gate[cM * cDV];
__device__ float g_o[cM * cDV];
__device__ float g_kv[cNC * cBH * cDKH * cDVH];
__device__ float g_S[cNC * cBH * cDKH * cDVH];
__device__ float g_bdec[cNC * cBH * cDKH];
__device__ float g_gla[cM * cD];
__device__ float g_lora[cM * cRANK];
__device__ float g_hnew[cM * cD];
__device__ float g_hout[cM * cD];
__device__ float g_cum[cM];
__device__ float g_halt[cM];
__device__ float g_einj[cM * cD];

// bf16 hi/lo buffers
__device__ __align__(16) __nv_bfloat16 g_wqh[cD * cDK],  g_wql[cD * cDK];
__device__ __align__(16) __nv_bfloat16 g_wkh[cD * cDK],  g_wkl[cD * cDK];
__device__ __align__(16) __nv_bfloat16 g_wgkh[cD * cDK], g_wgkl[cD * cDK];
__device__ __align__(16) __nv_bfloat16 g_wvh[cD * cDV],  g_wvl[cD * cDV];
__device__ __align__(16) __nv_bfloat16 g_wgh[cD * cDV],  g_wgl[cD * cDV];
__device__ __align__(16) __nv_bfloat16 g_woh[cDV * cD],  g_wol[cDV * cD];
__device__ __align__(16) __nv_bfloat16 g_iah[cD * cD],   g_ial[cD * cD];
__device__ __align__(16) __nv_bfloat16 g_ibh[cD * cD],   g_ibl[cD * cD];
__device__ __align__(16) __nv_bfloat16 g_eh[cM * cD],    g_el[cM * cD];
__device__ __align__(16) __nv_bfloat16 g_xh[cM * cD],    g_xl[cM * cD];
__device__ __align__(16) __nv_bfloat16 g_hh2[cM * cD],   g_hl2[cM * cD];
__device__ __align__(16) __nv_bfloat16 g_oh[cM * cDV],   g_ol[cM * cDV];

// ---------------- helpers ----------------
__device__ __forceinline__ uint32_t s2u(const void* p) {
    uint32_t a;
    asm("{ .reg .u64 t; cvta.to.shared.u64 t, %1; cvt.u32.u64 %0, t; }" : "=r"(a) : "l"(p));
    return a;
}
__device__ __forceinline__ uint32_t sw128(uint32_t off) { return off ^ ((off >> 3) & 0x70); }

#define LDSM4(r, a) \
    asm volatile("ldmatrix.sync.aligned.m8n8.x4.shared.b16 {%0,%1,%2,%3}, [%4];" \
        : "=r"((r)[0]), "=r"((r)[1]), "=r"((r)[2]), "=r"((r)[3]) : "r"(a))

__device__ __forceinline__ void mma_bf16(float* d, const uint32_t* a, const uint32_t* b) {
    asm volatile("mma.sync.aligned.m16n8k16.row.col.f32.bf16.bf16.f32 "
        "{%0,%1,%2,%3}, {%4,%5,%6,%7}, {%8,%9}, {%0,%1,%2,%3};"
        : "+f"(d[0]), "+f"(d[1]), "+f"(d[2]), "+f"(d[3])
        : "r"(a[0]), "r"(a[1]), "r"(a[2]), "r"(a[3]), "r"(b[0]), "r"(b[1]));
}

// ---------------- mma.sync bf16 hi/lo GEMM: C = epi(A@B^T + Cinit) ----------------
// A: [M,K] bf16 hi/lo row-major; B: [N,K] bf16 hi/lo (K-major).
// CTA tile 128x128, K-chunk 64, 8 warps (warp tile 32x64), 3-stage cp.async.
constexpr int GTM = 128, GTN = 128, GKC = 64;
constexpr int TILE_B = 16384;             // one operand tile (128x64 bf16)
constexpr int STG_B = 4 * TILE_B;         // Ah, Al, Bh, Bl  = 64KB
constexpr int NSTG = 3;
constexpr int GEMM_SMEM = NSTG * STG_B;   // 196608

__global__ void __launch_bounds__(256, 1) gemm_bf16(
    const __nv_bfloat16* __restrict__ Ah, const __nv_bfloat16* __restrict__ Al,
    const __nv_bfloat16* __restrict__ Bh, const __nv_bfloat16* __restrict__ Bl,
    float* __restrict__ C, const float* __restrict__ Ci,
    int M, int N, int K, float scale, int epi)
{
    extern __shared__ char smem[];
    int tid = threadIdx.x;
    int lane = tid & 31, wid = tid >> 5;
    int m0 = blockIdx.y * GTM, n0 = blockIdx.x * GTN;
    int wm = (wid & 3) * 32, wn = (wid >> 2) * 64;

    const int NCk = K / GKC;

    auto load_stage = [&](int kc, int s) {
        char* base = smem + s * STG_B;
        int k0 = kc * GKC;
        const __nv_bfloat16* gp0 = Ah + (size_t)m0 * K + k0;
        const __nv_bfloat16* gp1 = Al + (size_t)m0 * K + k0;
        const __nv_bfloat16* gp2 = Bh + (size_t)n0 * K + k0;
        const __nv_bfloat16* gp3 = Bl + (size_t)n0 * K + k0;
#pragma unroll
        for (int i = 0; i < 4; i++) {
            int gg = tid + i * 256;                 // 0..1023
            int r = gg >> 3, seg = gg & 7;
            uint32_t off = sw128((uint32_t)(r * 128 + seg * 16));
            size_t go = (size_t)r * K + seg * 8;
            uint32_t d0 = s2u(base + off);
            uint32_t d1 = s2u(base + TILE_B + off);
            uint32_t d2 = s2u(base + 2 * TILE_B + off);
            uint32_t d3 = s2u(base + 3 * TILE_B + off);
            asm volatile("cp.async.cg.shared.global [%0], [%1], 16;" :: "r"(d0), "l"(gp0 + go));
            asm volatile("cp.async.cg.shared.global [%0], [%1], 16;" :: "r"(d1), "l"(gp1 + go));
            asm volatile("cp.async.cg.shared.global [%0], [%1], 16;" :: "r"(d2), "l"(gp2 + go));
            asm volatile("cp.async.cg.shared.global [%0], [%1], 16;" :: "r"(d3), "l"(gp3 + go));
        }
        asm volatile("cp.async.commit_group;" ::: "memory");
    };

    float acc[2][8][4];
#pragma unroll
    for (int mf = 0; mf < 2; mf++)
#pragma unroll
        for (int nf = 0; nf < 8; nf++)
#pragma unroll
            for (int j = 0; j < 4; j++) acc[mf][nf][j] = 0.f;

    load_stage(0, 0);
    load_stage(1, 1);
    load_stage(2, 2);

    // precomputed ldmatrix lane address components
    int a_row = (lane & 15);
    int a_col8 = (lane >> 4);               // 0/1 -> k half
    int b_row = (lane & 7) + ((lane >> 4) & 1) * 8;
    int b_col8 = (lane >> 3) & 1;

    for (int c = 0; c < NCk; c++) {
        asm volatile("cp.async.wait_group 2;" ::: "memory");
        __syncthreads();
        char* base = smem + (c % 3) * STG_B;
        uint32_t sAh = s2u(base), sAl = sAh + TILE_B, sBh = sAl + TILE_B, sBl = sBh + TILE_B;
#pragma unroll
        for (int kk = 0; kk < 4; kk++) {
            int k0 = kk * 16;
            uint32_t ah[2][4], al[2][4], bh[8][2], bl[8][2];
#pragma unroll
            for (int mf = 0; mf < 2; mf++) {
                uint32_t off = sw128((uint32_t)((wm + mf * 16 + a_row) * 128 + (k0 + a_col8 * 8) * 2));
                LDSM4(ah[mf], sAh + off);
                LDSM4(al[mf], sAl + off);
            }
#pragma unroll
            for (int nf = 0; nf < 4; nf++) {
                uint32_t off = sw128((uint32_t)((wn + nf * 16 + b_row) * 128 + (k0 + b_col8 * 8) * 2));
                uint32_t r[4];
                LDSM4(r, sBh + off);
                bh[nf * 2][0] = r[0]; bh[nf * 2][1] = r[1];
                bh[nf * 2 + 1][0] = r[2]; bh[nf * 2 + 1][1] = r[3];
                LDSM4(r, sBl + off);
                bl[nf * 2][0] = r[0]; bl[nf * 2][1] = r[1];
                bl[nf * 2 + 1][0] = r[2]; bl[nf * 2 + 1][1] = r[3];
            }
#pragma unroll
            for (int mf = 0; mf < 2; mf++)
#pragma unroll
                for (int nf = 0; nf < 8; nf++) {
                    mma_bf16(acc[mf][nf], ah[mf], bh[nf]);
                    mma_bf16(acc[mf][nf], ah[mf], bl[nf]);
                    mma_bf16(acc[mf][nf], al[mf], bh[nf]);
                }
        }
        __syncthreads();
        if (c + 3 < NCk) load_stage(c + 3, c % 3);
        else asm volatile("cp.async.commit_group;" ::: "memory");
    }

    // epilogue: direct stores, fused Cinit + activation
#pragma unroll
    for (int mf = 0; mf < 2; mf++) {
#pragma unroll
        for (int nf = 0; nf < 8; nf++) {
            int r0 = m0 + wm + mf * 16 + (lane >> 2);
            int cc = n0 + wn + nf * 8 + (lane & 3) * 2;
#pragma unroll
            for (int hh = 0; hh < 2; hh++) {
                int r = r0 + hh * 8;
                float vx = acc[mf][nf][hh * 2], vy = acc[mf][nf][hh * 2 + 1];
                size_t off = (size_t)r * N + cc;
                if (Ci) { vx += Ci[off]; vy += Ci[off + 1]; }
                if (epi == 1) { vx *= scale; vy *= scale; }
                else if (epi == 2) {
                    vx = (fminf(vx, 0.f) - log1pf(expf(-fabsf(vx)))) * 0.0625f;
                    vy = (fminf(vy, 0.f) - log1pf(expf(-fabsf(vy)))) * 0.0625f;
                } else if (epi == 3) {
                    vx = vx / (1.f + expf(-vx));
                    vy = vy / (1.f + expf(-vy));
                }
                float2 v = make_float2(vx, vy);
                *(float2*)&C[off] = v;
            }
        }
    }
}

// ---------------- utility kernels ----------------
__global__ void k_copy(float* __restrict__ dst, const float* __restrict__ src) {
    int idx = blockIdx.x * 256 + threadIdx.x;
    dst[idx] = src[idx];
}
__global__ void k_zero(float* __restrict__ dst) {
    int idx = blockIdx.x * 256 + threadIdx.x;
    dst[idx] = 0.f;
}
__global__ void k_zero_state(float* __restrict__ cum, float* __restrict__ halt) {
    int idx = blockIdx.x * 256 + threadIdx.x;
    cum[idx] = 0.f; halt[idx] = 0.f;
}

__device__ __forceinline__ void bsplit(float x, __nv_bfloat16& h, __nv_bfloat16& l) {
    h = __float2bfloat16(x);
    l = __float2bfloat16(x - __bfloat162float(h));
}

__global__ void k_split(const float* __restrict__ src, __nv_bfloat16* __restrict__ hi,
                        __nv_bfloat16* __restrict__ lo) {
    size_t i4 = ((size_t)blockIdx.x * 256 + threadIdx.x) * 4;
    float4 v = *(const float4*)(src + i4);
    __nv_bfloat16 h0, h1, h2, h3, l0, l1, l2, l3;
    bsplit(v.x, h0, l0); bsplit(v.y, h1, l1); bsplit(v.z, h2, l2); bsplit(v.w, h3, l3);
    hi[i4] = h0; hi[i4+1] = h1; hi[i4+2] = h2; hi[i4+3] = h3;
    lo[i4] = l0; lo[i4+1] = l1; lo[i4+2] = l2; lo[i4+3] = l3;
}
__global__ void k_gatesplit(const float* __restrict__ o, const float* __restrict__ gate,
                            __nv_bfloat16* __restrict__ hi, __nv_bfloat16* __restrict__ lo) {
    size_t i4 = ((size_t)blockIdx.x * 256 + threadIdx.x) * 4;
    float4 v = *(const float4*)(o + i4);
    float4 g = *(const float4*)(gate + i4);
    v.x *= g.x; v.y *= g.y; v.z *= g.z; v.w *= g.w;
    __nv_bfloat16 h0, h1, h2, h3, l0, l1, l2, l3;
    bsplit(v.x, h0, l0); bsplit(v.y, h1, l1); bsplit(v.z, h2, l2); bsplit(v.w, h3, l3);
    hi[i4] = h0; hi[i4+1] = h1; hi[i4+2] = h2; hi[i4+3] = h3;
    lo[i4] = l0; lo[i4+1] = l1; lo[i4+2] = l2; lo[i4+3] = l3;
}
// transpose-convert: W [K,N] fp32 -> out [N,K] bf16 hi/lo
__global__ void k_wconvT(const float* __restrict__ W, __nv_bfloat16* __restrict__ hi,
                         __nv_bfloat16* __restrict__ lo, int K, int N) {
    __shared__ float s[32][33];
    int n0 = blockIdx.x * 32, k0 = blockIdx.y * 32;
    int tx = threadIdx.x, ty = threadIdx.y;
#pragma unroll
    for (int i = 0; i < 4; i++) {
        int r = ty + i * 8;
        s[r][tx] = W[(size_t)(k0 + r) * N + n0 + tx];
    }
    __syncthreads();
#pragma unroll
    for (int i = 0; i < 4; i++) {
        int r = ty + i * 8;
        float v = s[tx][r];
        size_t o = (size_t)(n0 + r) * K + k0 + tx;
        __nv_bfloat16 h, l; bsplit(v, h, l);
        hi[o] = h; lo[o] = l;
    }
}

// ---------------- fused loop-embed + rmsnorm(h+e) + bf16 splits of x and h ----------------
__global__ void __launch_bounds__(256) k_prep(float* __restrict__ h, const float* __restrict__ e,
                                              const float* __restrict__ nw, const float* __restrict__ ltab,
                                              __nv_bfloat16* __restrict__ xh, __nv_bfloat16* __restrict__ xl,
                                              __nv_bfloat16* __restrict__ hh, __nv_bfloat16* __restrict__ hl) {
    int row = blockIdx.x; size_t base = (size_t)row * cD;
    int tid = threadIdx.x;
    if (tid < cLOOPD) h[base + tid] += ltab[tid];
    __syncthreads();
    float hv[4], vals[4]; float ss = 0.f;
#pragma unroll
    for (int i = 0; i < 4; i++) {
        int c = tid + i * 256;
        float hx = h[base + c];
        hv[i] = hx;
        float v = hx + e[base + c];
        vals[i] = v; ss += v * v;
    }
    __shared__ float red[256];
    red[tid] = ss; __syncthreads();
    for (int s = 128; s > 0; s >>= 1) { if (tid < s) red[tid] += red[tid + s]; __syncthreads(); }
    float rs = rsqrtf(red[0] * (1.f / cD) + 1e-6f);
#pragma unroll
    for (int i = 0; i < 4; i++) {
        int c = tid + i * 256;
        float x = vals[i] * rs * nw[c];
        __nv_bfloat16 a, b;
        bsplit(x, a, b); xh[base + c] = a; xl[base + c] = b;
        bsplit(hv[i], a, b); hh[base + c] = a; hl[base + c] = b;
    }
}

// ---------------- final rmsnorm ----------------
__global__ void __launch_bounds__(256) k_rmsnorm(const float* __restrict__ in, const float* __restrict__ nw,
                                                 float* __restrict__ out) {
    int row = blockIdx.x; size_t base = (size_t)row * cD;
    int tid = threadIdx.x;
    float vals[4]; float ss = 0.f;
#pragma unroll
    for (int i = 0; i < 4; i++) {
        int c = tid + i * 256;
        float v = in[base + c];
        vals[i] = v; ss += v * v;
    }
    __shared__ float red[256];
    red[tid] = ss; __syncthreads();
    for (int s = 128; s > 0; s >>= 1) { if (tid < s) red[tid] += red[tid + s]; __syncthreads(); }
    float rs = rsqrtf(red[0] * (1.f / cD) + 1e-6f);
#pragma unroll
    for (int i = 0; i < 4; i++) {
        int c = tid + i * 256;
        out[base + c] = vals[i] * rs * nw[c];
    }
}

// ---------------- GLA chunk kernel ----------------
constexpr int SMEM_CHUNK = 49408 * 4;
__global__ void __launch_bounds__(256) k_chunk(float* __restrict__ pq, const float* __restrict__ pk,
                                               const float* __restrict__ pla, const float* __restrict__ pv,
                                               float* __restrict__ po, float* __restrict__ pkv,
                                               float* __restrict__ pbdec) {
    extern __shared__ float sm[];
    float* s_cum = sm;
    float* s_qt = sm + 8192;
    float* s_kt = sm + 16384;     // stride 132
    float* s_kc = sm + 24832;
    float* s_v  = sm + 33024;
    float* s_A  = sm;

    int cidx = blockIdx.x;
    int c = cidx / cBH, bh = cidx - c * cBH;
    int b = bh >> 3, hh = bh & 7;
    int t0 = c * cCH;
    size_t qbase = ((size_t)b * cT + t0) * cDK + hh * cDKH;
    size_t vbase = ((size_t)b * cT + t0) * cDV + hh * cDVH;
    int tid = threadIdx.x;

    if (tid < 128) {
        int d = tid;
        float cum = 0.f;
        for (int i = 0; i < cCH; i++) {
            size_t off = qbase + (size_t)i * cDK + d;
            cum += pla[off];
            s_cum[i * 128 + d] = cum;
            s_qt[i * 128 + d] = pq[off] * expf(cum);
            s_kt[i * 132 + d] = pk[off] * expf(-cum);
            s_kc[i * 128 + d] = pk[off];
        }
        float latot = cum;
        pbdec[(size_t)cidx * cDKH + d] = expf(latot);
        for (int i = 0; i < cCH; i++)
            s_kc[i * 128 + d] *= expf(latot - s_cum[i * 128 + d]);
        for (int i = 0; i < cCH; i++)
            pq[qbase + (size_t)i * cDK + d] = s_qt[i * 128 + d];
    } else {
        int lt = tid - 128;
        for (int l = 0; l < 32; l++) {
            int idx4 = lt + l * 128;
            int i = idx4 >> 6;
            int u4 = (idx4 & 63) * 4;
            *(float4*)&s_v[i * 256 + u4] = *(const float4*)&pv[vbase + (size_t)i * cDV + u4];
        }
    }
    __syncthreads();

    for (int idx = tid; idx < cCH * cCH; idx += 256) {
        int i = idx >> 6, j = idx & 63;
        float sum = 0.f;
        if (j <= i) {
            const float* qp = &s_qt[i * 128];
            const float* kp = &s_kt[j * 132];
#pragma unroll
            for (int d = 0; d < 128; d += 4) {
                float4 qa = *(const float4*)&qp[d];
                float4 kb = *(const float4*)&kp[d];
                sum += qa.x * kb.x + qa.y * kb.y + qa.z * kb.z + qa.w * kb.w;
            }
        }
        s_A[idx] = sum;
    }
    __syncthreads();

    for (int idx = tid; idx < cCH * cDVH; idx += 256) {
        int i = idx >> 8, u = idx & 255;
        float sum = 0.f;
        for (int j = 0; j <= i; j++) sum += s_A[i * 64 + j] * s_v[j * 256 + u];
        po[vbase + (size_t)i * cDV + u] = sum;
    }

    for (int idx = tid; idx < cDKH * cDVH; idx += 256) {
        int d = idx >> 8, u = idx & 255;
        float sum = 0.f;
#pragma unroll 8
        for (int i = 0; i < cCH; i++) sum += s_kc[i * 128 + d] * s_v[i * 256 + u];
        pkv[(size_t)cidx * (cDKH * cDVH) + idx] = sum;
    }
}

// ---------------- state propagation ----------------
__global__ void __launch_bounds__(256) k_state(const float* __restrict__ pkv, const float* __restrict__ pbdec,
                                               float* __restrict__ Sout) {
    int blk = blockIdx.x;
    int bh = blk >> 3;
    int vs = (blk & 7) * 32;
    int tid = threadIdx.x;
    int kr = tid >> 1;
    int vofs = vs + (tid & 1) * 16;
    float S[16];
#pragma unroll
    for (int j = 0; j < 16; j++) S[j] = 0.f;
    for (int c = 0; c < cNC; c++) {
        size_t base = ((size_t)c * cBH + bh) * (cDKH * cDVH) + (size_t)kr * cDVH + vofs;
        float bd = pbdec[((size_t)c * cBH + bh) * cDKH + kr];
#pragma unroll
        for (int j = 0; j < 16; j += 4) {
            *(float4*)&Sout[base + j] = make_float4(S[j], S[j + 1], S[j + 2], S[j + 3]);
            float4 kvv = *(const float4*)&pkv[base + j];
            S[j]     = bd * S[j]     + kvv.x;
            S[j + 1] = bd * S[j + 1] + kvv.y;
            S[j + 2] = bd * S[j + 2] + kvv.z;
            S[j + 3] = bd * S[j + 3] + kvv.w;
        }
    }
}

// ---------------- inter-chunk output ----------------
__global__ void __launch_bounds__(256) k_inter(const float* __restrict__ pq, const float* __restrict__ S,
                                               float* __restrict__ po) {
    __shared__ float s_q[cCH * cDKH];
    int cidx = blockIdx.x;
    int c = cidx / cBH, bh = cidx - c * cBH;
    int b = bh >> 3, hh = bh & 7;
    int t0 = c * cCH;
    size_t qbase = ((size_t)b * cT + t0) * cDK + hh * cDKH;
    size_t vbase = ((size_t)b * cT + t0) * cDV + hh * cDVH;
    int tid = threadIdx.x;
#pragma unroll
    for (int l = 0; l < 8; l++) {
        int idx4 = tid + l * 256;
        int i = idx4 >> 5;
        int d4 = (idx4 & 31) * 4;
        *(float4*)&s_q[i * 128 + d4] = *(const float4*)&pq[qbase + (size_t)i * cDK + d4];
    }
    __syncthreads();
    int u = tid;
    float acc[cCH];
#pragma unroll
    for (int i = 0; i < cCH; i++) acc[i] = 0.f;
    size_t sbase = (size_t)cidx * (cDKH * cDVH) + u;
    for (int d = 0; d < cDKH; d += 4) {
        float sv0 = S[sbase + (size_t)(d + 0) * cDVH];
        float sv1 = S[sbase + (size_t)(d + 1) * cDVH];
        float sv2 = S[sbase + (size_t)(d + 2) * cDVH];
        float sv3 = S[sbase + (size_t)(d + 3) * cDVH];
#pragma unroll
        for (int i = 0; i < cCH; i++) {
            float4 qv = *(const float4*)&s_q[i * 128 + d];
            acc[i] += qv.x * sv0 + qv.y * sv1 + qv.z * sv2 + qv.w * sv3;
        }
    }
#pragma unroll
    for (int i = 0; i < cCH; i++) {
        size_t off = vbase + (size_t)i * cDV + u;
        po[off] += acc[i];
    }
}

// ---------------- LoRA ----------------
__global__ void __launch_bounds__(256) k_lora_down(const float* __restrict__ g, const float* __restrict__ A,
                                                   float* __restrict__ out) {
    int warp = threadIdx.x >> 5, lane = threadIdx.x & 31;
    int m = blockIdx.x * 8 + warp;
    const float* grow = &g[(size_t)m * cD];
    float acc[cRANK];
#pragma unroll
    for (int r = 0; r < cRANK; r++) acc[r] = 0.f;
    for (int kk = lane; kk < cD; kk += 32) {
        float a = grow[kk];
        const float4* Ap = (const float4*)&A[(size_t)kk * cRANK];
        float4 b0 = Ap[0], b1 = Ap[1], b2 = Ap[2], b3 = Ap[3];
        acc[0] += a * b0.x; acc[1] += a * b0.y; acc[2] += a * b0.z; acc[3] += a * b0.w;
        acc[4] += a * b1.x; acc[5] += a * b1.y; acc[6] += a * b1.z; acc[7] += a * b1.w;
        acc[8] += a * b2.x; acc[9] += a * b2.y; acc[10] += a * b2.z; acc[11] += a * b2.w;
        acc[12] += a * b3.x; acc[13] += a * b3.y; acc[14] += a * b3.z; acc[15] += a * b3.w;
    }
#pragma unroll
    for (int r = 0; r < cRANK; r++)
        for (int s = 16; s > 0; s >>= 1) acc[r] += __shfl_xor_sync(0xffffffffu, acc[r], s);
    if (lane == 0) {
#pragma unroll
        for (int r = 0; r < cRANK; r++) out[(size_t)m * cRANK + r] = acc[r];
    }
}
// g += (g@A)@B + einj    (einj added AFTER lora-down consumed pure g)
__global__ void __launch_bounds__(256) k_lora_up(const float* __restrict__ tmp, const float* __restrict__ Bm,
                                                 const float* __restrict__ einj, float* __restrict__ g) {
    int idx = blockIdx.x * 256 + threadIdx.x;
    int m = idx >> 10, n = idx & 1023;
    const float* tr = &tmp[(size_t)m * cRANK];
    float s = 0.f;
#pragma unroll
    for (int r = 0; r < cRANK; r++) s += tr[r] * Bm[r * cD + n];
    g[idx] += s + einj[idx];
}

// ---------------- ACT halting ----------------
__global__ void __launch_bounds__(256) k_act(const float* __restrict__ hnew, const float* __restrict__ act_w,
                                             const float* __restrict__ act_b, float* __restrict__ h,
                                             float* __restrict__ hout, float* __restrict__ cum,
                                             float* __restrict__ halt) {
    int row = blockIdx.x; size_t base = (size_t)row * cD;
    int tid = threadIdx.x;
    float ss = 0.f;
#pragma unroll
    for (int i = 0; i < 4; i++) {
        int c = tid + i * 256;
        ss += hnew[base + c] * act_w[c];
    }
    __shared__ float red[256]; __shared__ float wsh;
    red[tid] = ss; __syncthreads();
    for (int s = 128; s > 0; s >>= 1) { if (tid < s) red[tid] += red[tid + s]; __syncthreads(); }
    if (tid == 0) {
        float z = red[0] + act_b[0];
        float p = 1.f / (1.f + expf(-z));
        float cm = cum[row]; float hl = halt[row];
        float p_eff = (hl > 0.5f) ? 0.f : p;
        float ncum = cm + p_eff;
        bool newly = (hl < 0.5f) && (ncum >= 0.99f);
        float w = newly ? (1.f - cm) : p_eff;
        cum[row] = ncum;
        if (newly) halt[row] = 1.f;
        wsh = w;
    }
    __syncthreads();
    float w = wsh;
#pragma unroll
    for (int i = 0; i < 4; i++) {
        int c = tid + i * 256;
        float v = hnew[base + c];
        hout[base + c] += w * v;
        h[base + c] = v;
    }
}

// ---------------- host ----------------
static void gemmB(const __nv_bfloat16* Ah, const __nv_bfloat16* Al,
                  const __nv_bfloat16* Bh, const __nv_bfloat16* Bl,
                  float* C, const float* Ci, int M, int N, int K, float scale, int epi) {
    dim3 g(N / GTN, M / GTM);
    gemm_bf16<<<g, 256, GEMM_SMEM>>>(Ah, Al, Bh, Bl, C, Ci, M, N, K, scale, epi);
}

extern "C" void kernel_launch(void* const* d_in, const int* in_sizes, int n_in,
                              void* d_out, int out_size) {
    const float* in_h  = (const float*)d_in[0];
    const float* in_e  = (const float*)d_in[1];
    const float* nw    = (const float*)d_in[2];
    const float* onw   = (const float*)d_in[3];
    const float* Wq    = (const float*)d_in[4];
    const float* Wk    = (const float*)d_in[5];
    const float* Wv    = (const float*)d_in[6];
    const float* Wgk   = (const float*)d_in[7];
    const float* Wg    = (const float*)d_in[8];
    const float* Wo    = (const float*)d_in[9];
    const float* loraA = (const float*)d_in[10];
    const float* loraB = (const float*)d_in[11];
    const float* injA  = (const float*)d_in[12];
    const float* injB  = (const float*)d_in[13];
    const float* act_w = (const float*)d_in[14];
    const float* act_b = (const float*)d_in[15];
    const float* ltab  = (const float*)d_in[16];
    float* out = (float*)d_out;

    float *p_h, *p_q, *p_k, *p_la, *p_v, *p_gate, *p_o, *p_kv, *p_S, *p_bdec,
          *p_gla, *p_lora, *p_hnew, *p_hout, *p_cum, *p_halt, *p_einj;
    cudaGetSymbolAddress((void**)&p_h, g_h);
    cudaGetSymbolAddress((void**)&p_q, g_q);
    cudaGetSymbolAddress((void**)&p_k, g_k);
    cudaGetSymbolAddress((void**)&p_la, g_la);
    cudaGetSymbolAddress((void**)&p_v, g_v);
    cudaGetSymbolAddress((void**)&p_gate, g_gate);
    cudaGetSymbolAddress((void**)&p_o, g_o);
    cudaGetSymbolAddress((void**)&p_kv, g_kv);
    cudaGetSymbolAddress((void**)&p_S, g_S);
    cudaGetSymbolAddress((void**)&p_bdec, g_bdec);
    cudaGetSymbolAddress((void**)&p_gla, g_gla);
    cudaGetSymbolAddress((void**)&p_lora, g_lora);
    cudaGetSymbolAddress((void**)&p_hnew, g_hnew);
    cudaGetSymbolAddress((void**)&p_hout, g_hout);
    cudaGetSymbolAddress((void**)&p_cum, g_cum);
    cudaGetSymbolAddress((void**)&p_halt, g_halt);
    cudaGetSymbolAddress((void**)&p_einj, g_einj);

    __nv_bfloat16 *wqh, *wql, *wkh, *wkl, *wgkh, *wgkl, *wvh, *wvl, *wgh, *wgl,
                  *woh, *wol, *iah, *ial, *ibh, *ibl, *eh, *el, *xh, *xl, *hh, *hl, *oh, *ol;
    cudaGetSymbolAddress((void**)&wqh, g_wqh);  cudaGetSymbolAddress((void**)&wql, g_wql);
    cudaGetSymbolAddress((void**)&wkh, g_wkh);  cudaGetSymbolAddress((void**)&wkl, g_wkl);
    cudaGetSymbolAddress((void**)&wgkh, g_wgkh); cudaGetSymbolAddress((void**)&wgkl, g_wgkl);
    cudaGetSymbolAddress((void**)&wvh, g_wvh);  cudaGetSymbolAddress((void**)&wvl, g_wvl);
    cudaGetSymbolAddress((void**)&wgh, g_wgh);  cudaGetSymbolAddress((void**)&wgl, g_wgl);
    cudaGetSymbolAddress((void**)&woh, g_woh);  cudaGetSymbolAddress((void**)&wol, g_wol);
    cudaGetSymbolAddress((void**)&iah, g_iah);  cudaGetSymbolAddress((void**)&ial, g_ial);
    cudaGetSymbolAddress((void**)&ibh, g_ibh);  cudaGetSymbolAddress((void**)&ibl, g_ibl);
    cudaGetSymbolAddress((void**)&eh, g_eh);    cudaGetSymbolAddress((void**)&el, g_el);
    cudaGetSymbolAddress((void**)&xh, g_xh);    cudaGetSymbolAddress((void**)&xl, g_xl);
    cudaGetSymbolAddress((void**)&hh, g_hh2);   cudaGetSymbolAddress((void**)&hl, g_hl2);
    cudaGetSymbolAddress((void**)&oh, g_oh);    cudaGetSymbolAddress((void**)&ol, g_ol);

    cudaFuncSetAttribute(k_chunk, cudaFuncAttributeMaxDynamicSharedMemorySize, SMEM_CHUNK);
    cudaFuncSetAttribute(gemm_bf16, cudaFuncAttributeMaxDynamicSharedMemorySize, GEMM_SMEM);

    const int nBig = cM * cD / 256;
    k_copy<<<nBig, 256>>>(p_h, in_h);
    k_zero<<<nBig, 256>>>(p_hout);
    k_zero_state<<<cM / 256, 256>>>(p_cum, p_halt);

    // weight conversions (transposed to [N,K] bf16 hi/lo)
    dim3 tb(32, 8);
    k_wconvT<<<dim3(cDK / 32, cD / 32), tb>>>(Wq,  wqh,  wql,  cD, cDK);
    k_wconvT<<<dim3(cDK / 32, cD / 32), tb>>>(Wk,  wkh,  wkl,  cD, cDK);
    k_wconvT<<<dim3(cDK / 32, cD / 32), tb>>>(Wgk, wgkh, wgkl, cD, cDK);
    k_wconvT<<<dim3(cDV / 32, cD / 32), tb>>>(Wv,  wvh,  wvl,  cD, cDV);
    k_wconvT<<<dim3(cDV / 32, cD / 32), tb>>>(Wg,  wgh,  wgl,  cD, cDV);
    k_wconvT<<<dim3(cD / 32, cDV / 32), tb>>>(Wo,  woh,  wol,  cDV, cD);
    // injA / injB used directly as K-major B (Bt[n][k] = inj[n][k])
    k_split<<<cD * cD / 1024, 256>>>(injA, iah, ial);
    k_split<<<cD * cD / 1024, 256>>>(injB, ibh, ibl);
    k_split<<<cM * cD / 1024, 256>>>(in_e, eh, el);

    // loop-invariant: einj = e @ injB^T
    gemmB(eh, el, ibh, ibl, p_einj, nullptr, cM, cD, cD, 0.f, 0);

    const float qscale = 0.08838834764831845f;

    for (int t = 0; t < cNL; t++) {
        k_prep<<<cM, 256>>>(p_h, in_e, nw, ltab + t * cLOOPD, xh, xl, hh, hl);

        gemmB(xh, xl, wqh,  wql,  p_q,    nullptr, cM, cDK, cD, qscale, 1);
        gemmB(xh, xl, wkh,  wkl,  p_k,    nullptr, cM, cDK, cD, 0.f, 0);
        gemmB(xh, xl, wgkh, wgkl, p_la,   nullptr, cM, cDK, cD, 0.f, 2);
        gemmB(xh, xl, wvh,  wvl,  p_v,    nullptr, cM, cDV, cD, 0.f, 0);
        gemmB(xh, xl, wgh,  wgl,  p_gate, nullptr, cM, cDV, cD, 0.f, 3);

        k_chunk<<<cNC * cBH, 256, SMEM_CHUNK>>>(p_q, p_k, p_la, p_v, p_o, p_kv, p_bdec);
        k_state<<<cBH * 8, 256>>>(p_kv, p_bdec, p_S);
        k_inter<<<cNC * cBH, 256>>>(p_q, p_S, p_o);

        // pure g = (o*silu(gate)) @ Wo^T   (NO einj here — LoRA must see pure g)
        k_gatesplit<<<cM * cDV / 1024, 256>>>(p_o, p_gate, oh, ol);
        gemmB(oh, ol, woh, wol, p_gla, nullptr, cM, cD, cDV, 0.f, 0);

        k_lora_down<<<cM / 8, 256>>>(p_gla, loraA + (size_t)t * cD * cRANK, p_lora);
        k_lora_up<<<nBig, 256>>>(p_lora, loraB + (size_t)t * cRANK * cD, p_einj, p_gla);

        gemmB(hh, hl, iah, ial, p_hnew, p_gla, cM, cD, cD, 0.f, 0);

        k_act<<<cM, 256>>>(p_hnew, act_w, act_b, p_h, p_hout, p_cum, p_halt);
    }
    k_rmsnorm<<<cM, 256>>>(p_hout, onw, out);
}

// round 7
// speedup vs baseline: 2.9564x; 1.2378x over previous
#include <cuda_runtime.h>
#include <cuda_bf16.h>
#include <math.h>
#include <stdint.h>

// ---------------- problem constants ----------------
constexpr int cB = 4, cT = 4096, cD = 1024, cH = 8;
constexpr int cDK = 1024, cDV = 2048, cDKH = 128, cDVH = 256;
constexpr int cRANK = 16, cLOOPD = 128, cNL = 4;
constexpr int cCH = 64;                 // GLA chunk length
constexpr int cNC = cT / cCH;           // 64 chunks
constexpr int cBH = cB * cH;            // 32
constexpr int cM = cB * cT;             // 16384 rows

// ---------------- device scratch ----------------
__device__ float g_h[cM * cD];
__device__ float g_q[cM * cDK];
__device__ float g_k[cM * cDK];
__device__ float g_la[cM * cDK];
__device__ float g_v[cM * cDV];
__device__ float g_gate[cM * cDV];
__device__ float g_o[cM * cDV];
__device__ float g_kv[cNC * cBH * cDKH * cDVH];
__device__ float g_S[cNC * cBH * cDKH * cDVH];
__device__ float g_bdec[cNC * cBH * cDKH];
__device__ float g_gla[cM * cD];
__device__ float g_lora[cM * cRANK];
__device__ float g_hnew[cM * cD];
__device__ float g_hout[cM * cD];
__device__ float g_cum[cM];
__device__ float g_halt[cM];
__device__ float g_einj[cM * cD];

// bf16 hi/lo buffers
__device__ __align__(16) __nv_bfloat16 g_wqh[cD * cDK],  g_wql[cD * cDK];
__device__ __align__(16) __nv_bfloat16 g_wkh[cD * cDK],  g_wkl[cD * cDK];
__device__ __align__(16) __nv_bfloat16 g_wgkh[cD * cDK], g_wgkl[cD * cDK];
__device__ __align__(16) __nv_bfloat16 g_wvh[cD * cDV],  g_wvl[cD * cDV];
__device__ __align__(16) __nv_bfloat16 g_wgh[cD * cDV],  g_wgl[cD * cDV];
__device__ __align__(16) __nv_bfloat16 g_woh[cDV * cD],  g_wol[cDV * cD];
__device__ __align__(16) __nv_bfloat16 g_iah[cD * cD],   g_ial[cD * cD];
__device__ __align__(16) __nv_bfloat16 g_ibh[cD * cD],   g_ibl[cD * cD];
__device__ __align__(16) __nv_bfloat16 g_eh[cM * cD],    g_el[cM * cD];
__device__ __align__(16) __nv_bfloat16 g_xh[cM * cD],    g_xl[cM * cD];
__device__ __align__(16) __nv_bfloat16 g_hh2[cM * cD],   g_hl2[cM * cD];
__device__ __align__(16) __nv_bfloat16 g_oh[cM * cDV],   g_ol[cM * cDV];

// ---------------- helpers ----------------
__device__ __forceinline__ uint32_t s2u(const void* p) {
    uint32_t a;
    asm("{ .reg .u64 t; cvta.to.shared.u64 t, %1; cvt.u32.u64 %0, t; }" : "=r"(a) : "l"(p));
    return a;
}
__device__ __forceinline__ uint32_t sw128(uint32_t off) { return off ^ ((off >> 3) & 0x70); }

#define LDSM4(r, a) \
    asm volatile("ldmatrix.sync.aligned.m8n8.x4.shared.b16 {%0,%1,%2,%3}, [%4];" \
        : "=r"((r)[0]), "=r"((r)[1]), "=r"((r)[2]), "=r"((r)[3]) : "r"(a))

__device__ __forceinline__ void mma_bf16(float* d, const uint32_t* a, const uint32_t* b) {
    asm volatile("mma.sync.aligned.m16n8k16.row.col.f32.bf16.bf16.f32 "
        "{%0,%1,%2,%3}, {%4,%5,%6,%7}, {%8,%9}, {%0,%1,%2,%3};"
        : "+f"(d[0]), "+f"(d[1]), "+f"(d[2]), "+f"(d[3])
        : "r"(a[0]), "r"(a[1]), "r"(a[2]), "r"(a[3]), "r"(b[0]), "r"(b[1]));
}

// ---------------- mma.sync bf16 hi/lo GEMM: C = epi(A@B^T + Cinit) ----------------
constexpr int GTM = 128, GTN = 128, GKC = 64;
constexpr int TILE_B = 16384;
constexpr int STG_B = 4 * TILE_B;
constexpr int NSTG = 3;
constexpr int GEMM_SMEM = NSTG * STG_B;   // 196608

__global__ void __launch_bounds__(256, 1) gemm_bf16(
    const __nv_bfloat16* __restrict__ Ah, const __nv_bfloat16* __restrict__ Al,
    const __nv_bfloat16* __restrict__ Bh, const __nv_bfloat16* __restrict__ Bl,
    float* __restrict__ C, const float* __restrict__ Ci,
    int M, int N, int K, float scale, int epi)
{
    extern __shared__ char smem[];
    int tid = threadIdx.x;
    int lane = tid & 31, wid = tid >> 5;
    int m0 = blockIdx.y * GTM, n0 = blockIdx.x * GTN;
    int wm = (wid & 3) * 32, wn = (wid >> 2) * 64;

    const int NCk = K / GKC;

    auto load_stage = [&](int kc, int s) {
        char* base = smem + s * STG_B;
        int k0 = kc * GKC;
        const __nv_bfloat16* gp0 = Ah + (size_t)m0 * K + k0;
        const __nv_bfloat16* gp1 = Al + (size_t)m0 * K + k0;
        const __nv_bfloat16* gp2 = Bh + (size_t)n0 * K + k0;
        const __nv_bfloat16* gp3 = Bl + (size_t)n0 * K + k0;
#pragma unroll
        for (int i = 0; i < 4; i++) {
            int gg = tid + i * 256;
            int r = gg >> 3, seg = gg & 7;
            uint32_t off = sw128((uint32_t)(r * 128 + seg * 16));
            size_t go = (size_t)r * K + seg * 8;
            uint32_t d0 = s2u(base + off);
            uint32_t d1 = s2u(base + TILE_B + off);
            uint32_t d2 = s2u(base + 2 * TILE_B + off);
            uint32_t d3 = s2u(base + 3 * TILE_B + off);
            asm volatile("cp.async.cg.shared.global [%0], [%1], 16;" :: "r"(d0), "l"(gp0 + go));
            asm volatile("cp.async.cg.shared.global [%0], [%1], 16;" :: "r"(d1), "l"(gp1 + go));
            asm volatile("cp.async.cg.shared.global [%0], [%1], 16;" :: "r"(d2), "l"(gp2 + go));
            asm volatile("cp.async.cg.shared.global [%0], [%1], 16;" :: "r"(d3), "l"(gp3 + go));
        }
        asm volatile("cp.async.commit_group;" ::: "memory");
    };

    float acc[2][8][4];
#pragma unroll
    for (int mf = 0; mf < 2; mf++)
#pragma unroll
        for (int nf = 0; nf < 8; nf++)
#pragma unroll
            for (int j = 0; j < 4; j++) acc[mf][nf][j] = 0.f;

    load_stage(0, 0);
    load_stage(1, 1);
    load_stage(2, 2);

    int a_row = (lane & 15);
    int a_col8 = (lane >> 4);
    int b_row = (lane & 7) + ((lane >> 4) & 1) * 8;
    int b_col8 = (lane >> 3) & 1;

    for (int c = 0; c < NCk; c++) {
        asm volatile("cp.async.wait_group 2;" ::: "memory");
        __syncthreads();
        char* base = smem + (c % 3) * STG_B;
        uint32_t sAh = s2u(base), sAl = sAh + TILE_B, sBh = sAl + TILE_B, sBl = sBh + TILE_B;
#pragma unroll
        for (int kk = 0; kk < 4; kk++) {
            int k0 = kk * 16;
            uint32_t ah[2][4], al[2][4], bh[8][2], bl[8][2];
#pragma unroll
            for (int mf = 0; mf < 2; mf++) {
                uint32_t off = sw128((uint32_t)((wm + mf * 16 + a_row) * 128 + (k0 + a_col8 * 8) * 2));
                LDSM4(ah[mf], sAh + off);
                LDSM4(al[mf], sAl + off);
            }
#pragma unroll
            for (int nf = 0; nf < 4; nf++) {
                uint32_t off = sw128((uint32_t)((wn + nf * 16 + b_row) * 128 + (k0 + b_col8 * 8) * 2));
                uint32_t r[4];
                LDSM4(r, sBh + off);
                bh[nf * 2][0] = r[0]; bh[nf * 2][1] = r[1];
                bh[nf * 2 + 1][0] = r[2]; bh[nf * 2 + 1][1] = r[3];
                LDSM4(r, sBl + off);
                bl[nf * 2][0] = r[0]; bl[nf * 2][1] = r[1];
                bl[nf * 2 + 1][0] = r[2]; bl[nf * 2 + 1][1] = r[3];
            }
#pragma unroll
            for (int mf = 0; mf < 2; mf++)
#pragma unroll
                for (int nf = 0; nf < 8; nf++) {
                    mma_bf16(acc[mf][nf], ah[mf], bh[nf]);
                    mma_bf16(acc[mf][nf], ah[mf], bl[nf]);
                    mma_bf16(acc[mf][nf], al[mf], bh[nf]);
                }
        }
        __syncthreads();
        if (c + 3 < NCk) load_stage(c + 3, c % 3);
        else asm volatile("cp.async.commit_group;" ::: "memory");
    }

#pragma unroll
    for (int mf = 0; mf < 2; mf++) {
#pragma unroll
        for (int nf = 0; nf < 8; nf++) {
            int r0 = m0 + wm + mf * 16 + (lane >> 2);
            int cc = n0 + wn + nf * 8 + (lane & 3) * 2;
#pragma unroll
            for (int hh = 0; hh < 2; hh++) {
                int r = r0 + hh * 8;
                float vx = acc[mf][nf][hh * 2], vy = acc[mf][nf][hh * 2 + 1];
                size_t off = (size_t)r * N + cc;
                if (Ci) { vx += Ci[off]; vy += Ci[off + 1]; }
                if (epi == 1) { vx *= scale; vy *= scale; }
                else if (epi == 2) {
                    vx = (fminf(vx, 0.f) - log1pf(expf(-fabsf(vx)))) * 0.0625f;
                    vy = (fminf(vy, 0.f) - log1pf(expf(-fabsf(vy)))) * 0.0625f;
                } else if (epi == 3) {
                    vx = vx / (1.f + expf(-vx));
                    vy = vy / (1.f + expf(-vy));
                }
                float2 v = make_float2(vx, vy);
                *(float2*)&C[off] = v;
            }
        }
    }
}

// ---------------- utility kernels ----------------
__global__ void k_copy(float* __restrict__ dst, const float* __restrict__ src) {
    int idx = blockIdx.x * 256 + threadIdx.x;
    dst[idx] = src[idx];
}
__global__ void k_zero(float* __restrict__ dst) {
    int idx = blockIdx.x * 256 + threadIdx.x;
    dst[idx] = 0.f;
}
__global__ void k_zero_state(float* __restrict__ cum, float* __restrict__ halt) {
    int idx = blockIdx.x * 256 + threadIdx.x;
    cum[idx] = 0.f; halt[idx] = 0.f;
}

__device__ __forceinline__ void bsplit(float x, __nv_bfloat16& h, __nv_bfloat16& l) {
    h = __float2bfloat16(x);
    l = __float2bfloat16(x - __bfloat162float(h));
}

__global__ void k_split(const float* __restrict__ src, __nv_bfloat16* __restrict__ hi,
                        __nv_bfloat16* __restrict__ lo) {
    size_t i4 = ((size_t)blockIdx.x * 256 + threadIdx.x) * 4;
    float4 v = *(const float4*)(src + i4);
    __nv_bfloat16 h0, h1, h2, h3, l0, l1, l2, l3;
    bsplit(v.x, h0, l0); bsplit(v.y, h1, l1); bsplit(v.z, h2, l2); bsplit(v.w, h3, l3);
    hi[i4] = h0; hi[i4+1] = h1; hi[i4+2] = h2; hi[i4+3] = h3;
    lo[i4] = l0; lo[i4+1] = l1; lo[i4+2] = l2; lo[i4+3] = l3;
}
// transpose-convert: W [K,N] fp32 -> out [N,K] bf16 hi/lo
__global__ void k_wconvT(const float* __restrict__ W, __nv_bfloat16* __restrict__ hi,
                         __nv_bfloat16* __restrict__ lo, int K, int N) {
    __shared__ float s[32][33];
    int n0 = blockIdx.x * 32, k0 = blockIdx.y * 32;
    int tx = threadIdx.x, ty = threadIdx.y;
#pragma unroll
    for (int i = 0; i < 4; i++) {
        int r = ty + i * 8;
        s[r][tx] = W[(size_t)(k0 + r) * N + n0 + tx];
    }
    __syncthreads();
#pragma unroll
    for (int i = 0; i < 4; i++) {
        int r = ty + i * 8;
        float v = s[tx][r];
        size_t o = (size_t)(n0 + r) * K + k0 + tx;
        __nv_bfloat16 h, l; bsplit(v, h, l);
        hi[o] = h; lo[o] = l;
    }
}

// ---------------- fused loop-embed + rmsnorm(h+e) + bf16 splits of x and h ----------------
__global__ void __launch_bounds__(256) k_prep(float* __restrict__ h, const float* __restrict__ e,
                                              const float* __restrict__ nw, const float* __restrict__ ltab,
                                              __nv_bfloat16* __restrict__ xh, __nv_bfloat16* __restrict__ xl,
                                              __nv_bfloat16* __restrict__ hh, __nv_bfloat16* __restrict__ hl) {
    int row = blockIdx.x; size_t base = (size_t)row * cD;
    int tid = threadIdx.x;
    if (tid < cLOOPD) h[base + tid] += ltab[tid];
    __syncthreads();
    float hv[4], vals[4]; float ss = 0.f;
#pragma unroll
    for (int i = 0; i < 4; i++) {
        int c = tid + i * 256;
        float hx = h[base + c];
        hv[i] = hx;
        float v = hx + e[base + c];
        vals[i] = v; ss += v * v;
    }
    __shared__ float red[256];
    red[tid] = ss; __syncthreads();
    for (int s = 128; s > 0; s >>= 1) { if (tid < s) red[tid] += red[tid + s]; __syncthreads(); }
    float rs = rsqrtf(red[0] * (1.f / cD) + 1e-6f);
#pragma unroll
    for (int i = 0; i < 4; i++) {
        int c = tid + i * 256;
        float x = vals[i] * rs * nw[c];
        __nv_bfloat16 a, b;
        bsplit(x, a, b); xh[base + c] = a; xl[base + c] = b;
        bsplit(hv[i], a, b); hh[base + c] = a; hl[base + c] = b;
    }
}

// ---------------- final rmsnorm ----------------
__global__ void __launch_bounds__(256) k_rmsnorm(const float* __restrict__ in, const float* __restrict__ nw,
                                                 float* __restrict__ out) {
    int row = blockIdx.x; size_t base = (size_t)row * cD;
    int tid = threadIdx.x;
    float vals[4]; float ss = 0.f;
#pragma unroll
    for (int i = 0; i < 4; i++) {
        int c = tid + i * 256;
        float v = in[base + c];
        vals[i] = v; ss += v * v;
    }
    __shared__ float red[256];
    red[tid] = ss; __syncthreads();
    for (int s = 128; s > 0; s >>= 1) { if (tid < s) red[tid] += red[tid + s]; __syncthreads(); }
    float rs = rsqrtf(red[0] * (1.f / cD) + 1e-6f);
#pragma unroll
    for (int i = 0; i < 4; i++) {
        int c = tid + i * 256;
        out[base + c] = vals[i] * rs * nw[c];
    }
}

// ---------------- GLA chunk kernel (vectorized) ----------------
constexpr int SMEM_CHUNK = 49408 * 4;
__global__ void __launch_bounds__(256) k_chunk(float* __restrict__ pq, const float* __restrict__ pk,
                                               const float* __restrict__ pla, const float* __restrict__ pv,
                                               float* __restrict__ po, float* __restrict__ pkv,
                                               float* __restrict__ pbdec) {
    extern __shared__ float sm[];
    float* s_cum = sm;
    float* s_qt = sm + 8192;
    float* s_kt = sm + 16384;     // stride 132
    float* s_kc = sm + 24832;
    float* s_v  = sm + 33024;
    float* s_A  = sm;

    int cidx = blockIdx.x;
    int c = cidx / cBH, bh = cidx - c * cBH;
    int b = bh >> 3, hh = bh & 7;
    int t0 = c * cCH;
    size_t qbase = ((size_t)b * cT + t0) * cDK + hh * cDKH;
    size_t vbase = ((size_t)b * cT + t0) * cDV + hh * cDVH;
    int tid = threadIdx.x;

    if (tid < 128) {
        int d = tid;
        float cum = 0.f;
        for (int i = 0; i < cCH; i++) {
            size_t off = qbase + (size_t)i * cDK + d;
            cum += pla[off];
            s_cum[i * 128 + d] = cum;
            s_qt[i * 128 + d] = pq[off] * expf(cum);
            s_kt[i * 132 + d] = pk[off] * expf(-cum);
            s_kc[i * 128 + d] = pk[off];
        }
        float latot = cum;
        pbdec[(size_t)cidx * cDKH + d] = expf(latot);
        for (int i = 0; i < cCH; i++)
            s_kc[i * 128 + d] *= expf(latot - s_cum[i * 128 + d]);
        for (int i = 0; i < cCH; i++)
            pq[qbase + (size_t)i * cDK + d] = s_qt[i * 128 + d];
    } else {
        int lt = tid - 128;
        for (int l = 0; l < 32; l++) {
            int idx4 = lt + l * 128;
            int i = idx4 >> 6;
            int u4 = (idx4 & 63) * 4;
            *(float4*)&s_v[i * 256 + u4] = *(const float4*)&pv[vbase + (size_t)i * cDV + u4];
        }
    }
    __syncthreads();

    // A = mask(q~ k~^T)
    for (int idx = tid; idx < cCH * cCH; idx += 256) {
        int i = idx >> 6, j = idx & 63;
        float sum = 0.f;
        if (j <= i) {
            const float* qp = &s_qt[i * 128];
            const float* kp = &s_kt[j * 132];
#pragma unroll
            for (int d = 0; d < 128; d += 4) {
                float4 qa = *(const float4*)&qp[d];
                float4 kb = *(const float4*)&kp[d];
                sum += qa.x * kb.x + qa.y * kb.y + qa.z * kb.z + qa.w * kb.w;
            }
        }
        s_A[idx] = sum;
    }
    __syncthreads();

    // O_intra = A @ V   (warp-uniform row i; float4 on v)
    {
        int uq = tid & 63;            // u = uq*4
        int il = tid >> 6;            // 0..3 (uniform within warp)
#pragma unroll 1
        for (int step = 0; step < 16; step++) {
            int i = il + step * 4;
            float4 acc = make_float4(0.f, 0.f, 0.f, 0.f);
            const float* arow = &s_A[i * 64];
            for (int j = 0; j <= i; j++) {
                float a = arow[j];
                float4 vv = *(const float4*)&s_v[j * 256 + uq * 4];
                acc.x += a * vv.x; acc.y += a * vv.y; acc.z += a * vv.z; acc.w += a * vv.w;
            }
            *(float4*)&po[vbase + (size_t)i * cDV + uq * 4] = acc;
        }
    }

    // KV_c = kc^T @ V   (4x4 register block per slot: 2 LDS.128 per 16 FMA)
    {
#pragma unroll 1
        for (int s = 0; s < 8; s++) {
            int idx = tid + s * 256;          // 0..2047
            int dq = idx >> 6;                // 0..31  (uniform within warp)
            int uq = idx & 63;                // 0..63
            float4 a0 = make_float4(0.f,0.f,0.f,0.f), a1 = a0, a2 = a0, a3 = a0;
#pragma unroll 4
            for (int j = 0; j < cCH; j++) {
                float4 kc = *(const float4*)&s_kc[j * 128 + dq * 4];
                float4 vv = *(const float4*)&s_v[j * 256 + uq * 4];
                a0.x += kc.x * vv.x; a0.y += kc.x * vv.y; a0.z += kc.x * vv.z; a0.w += kc.x * vv.w;
                a1.x += kc.y * vv.x; a1.y += kc.y * vv.y; a1.z += kc.y * vv.z; a1.w += kc.y * vv.w;
                a2.x += kc.z * vv.x; a2.y += kc.z * vv.y; a2.z += kc.z * vv.z; a2.w += kc.z * vv.w;
                a3.x += kc.w * vv.x; a3.y += kc.w * vv.y; a3.z += kc.w * vv.z; a3.w += kc.w * vv.w;
            }
            size_t kvbase = (size_t)cidx * (cDKH * cDVH) + (size_t)(dq * 4) * cDVH + uq * 4;
            *(float4*)&pkv[kvbase]            = a0;
            *(float4*)&pkv[kvbase + cDVH]     = a1;
            *(float4*)&pkv[kvbase + 2 * cDVH] = a2;
            *(float4*)&pkv[kvbase + 3 * cDVH] = a3;
        }
    }
}

// ---------------- state propagation ----------------
__global__ void __launch_bounds__(256) k_state(const float* __restrict__ pkv, const float* __restrict__ pbdec,
                                               float* __restrict__ Sout) {
    int blk = blockIdx.x;
    int bh = blk >> 3;
    int vs = (blk & 7) * 32;
    int tid = threadIdx.x;
    int kr = tid >> 1;
    int vofs = vs + (tid & 1) * 16;
    float S[16];
#pragma unroll
    for (int j = 0; j < 16; j++) S[j] = 0.f;
    for (int c = 0; c < cNC; c++) {
        size_t base = ((size_t)c * cBH + bh) * (cDKH * cDVH) + (size_t)kr * cDVH + vofs;
        float bd = pbdec[((size_t)c * cBH + bh) * cDKH + kr];
#pragma unroll
        for (int j = 0; j < 16; j += 4) {
            *(float4*)&Sout[base + j] = make_float4(S[j], S[j + 1], S[j + 2], S[j + 3]);
            float4 kvv = *(const float4*)&pkv[base + j];
            S[j]     = bd * S[j]     + kvv.x;
            S[j + 1] = bd * S[j + 1] + kvv.y;
            S[j + 2] = bd * S[j + 2] + kvv.z;
            S[j + 3] = bd * S[j + 3] + kvv.w;
        }
    }
}

// ---------------- inter-chunk output + fused gate + bf16 split ----------------
__global__ void __launch_bounds__(256) k_inter(const float* __restrict__ pq, const float* __restrict__ S,
                                               const float* __restrict__ po, const float* __restrict__ pgate,
                                               __nv_bfloat16* __restrict__ oh, __nv_bfloat16* __restrict__ ol) {
    __shared__ float s_q[cCH * cDKH];
    int cidx = blockIdx.x;
    int c = cidx / cBH, bh = cidx - c * cBH;
    int b = bh >> 3, hh = bh & 7;
    int t0 = c * cCH;
    size_t qbase = ((size_t)b * cT + t0) * cDK + hh * cDKH;
    size_t vbase = ((size_t)b * cT + t0) * cDV + hh * cDVH;
    int tid = threadIdx.x;
#pragma unroll
    for (int l = 0; l < 8; l++) {
        int idx4 = tid + l * 256;
        int i = idx4 >> 5;
        int d4 = (idx4 & 31) * 4;
        *(float4*)&s_q[i * 128 + d4] = *(const float4*)&pq[qbase + (size_t)i * cDK + d4];
    }
    __syncthreads();
    int u = tid;
    float acc[cCH];
#pragma unroll
    for (int i = 0; i < cCH; i++) acc[i] = 0.f;
    size_t sbase = (size_t)cidx * (cDKH * cDVH) + u;
    for (int d = 0; d < cDKH; d += 4) {
        float sv0 = S[sbase + (size_t)(d + 0) * cDVH];
        float sv1 = S[sbase + (size_t)(d + 1) * cDVH];
        float sv2 = S[sbase + (size_t)(d + 2) * cDVH];
        float sv3 = S[sbase + (size_t)(d + 3) * cDVH];
#pragma unroll
        for (int i = 0; i < cCH; i++) {
            float4 qv = *(const float4*)&s_q[i * 128 + d];
            acc[i] += qv.x * sv0 + qv.y * sv1 + qv.z * sv2 + qv.w * sv3;
        }
    }
#pragma unroll
    for (int i = 0; i < cCH; i++) {
        size_t off = vbase + (size_t)i * cDV + u;
        float ov = (po[off] + acc[i]) * pgate[off];
        __nv_bfloat16 hbf, lbf; bsplit(ov, hbf, lbf);
        oh[off] = hbf; ol[off] = lbf;
    }
}

// ---------------- LoRA ----------------
__global__ void __launch_bounds__(256) k_lora_down(const float* __restrict__ g, const float* __restrict__ A,
                                                   float* __restrict__ out) {
    int warp = threadIdx.x >> 5, lane = threadIdx.x & 31;
    int m = blockIdx.x * 8 + warp;
    const float* grow = &g[(size_t)m * cD];
    float acc[cRANK];
#pragma unroll
    for (int r = 0; r < cRANK; r++) acc[r] = 0.f;
    for (int kk = lane; kk < cD; kk += 32) {
        float a = grow[kk];
        const float4* Ap = (const float4*)&A[(size_t)kk * cRANK];
        float4 b0 = Ap[0], b1 = Ap[1], b2 = Ap[2], b3 = Ap[3];
        acc[0] += a * b0.x; acc[1] += a * b0.y; acc[2] += a * b0.z; acc[3] += a * b0.w;
        acc[4] += a * b1.x; acc[5] += a * b1.y; acc[6] += a * b1.z; acc[7] += a * b1.w;
        acc[8] += a * b2.x; acc[9] += a * b2.y; acc[10] += a * b2.z; acc[11] += a * b2.w;
        acc[12] += a * b3.x; acc[13] += a * b3.y; acc[14] += a * b3.z; acc[15] += a * b3.w;
    }
#pragma unroll
    for (int r = 0; r < cRANK; r++)
        for (int s = 16; s > 0; s >>= 1) acc[r] += __shfl_xor_sync(0xffffffffu, acc[r], s);
    if (lane == 0) {
#pragma unroll
        for (int r = 0; r < cRANK; r++) out[(size_t)m * cRANK + r] = acc[r];
    }
}
// g += (g@A)@B + einj    (einj added AFTER lora-down consumed pure g)
__global__ void __launch_bounds__(256) k_lora_up(const float* __restrict__ tmp, const float* __restrict__ Bm,
                                                 const float* __restrict__ einj, float* __restrict__ g) {
    int idx = blockIdx.x * 256 + threadIdx.x;
    int m = idx >> 10, n = idx & 1023;
    const float* tr = &tmp[(size_t)m * cRANK];
    float s = 0.f;
#pragma unroll
    for (int r = 0; r < cRANK; r++) s += tr[r] * Bm[r * cD + n];
    g[idx] += s + einj[idx];
}

// ---------------- ACT halting ----------------
__global__ void __launch_bounds__(256) k_act(const float* __restrict__ hnew, const float* __restrict__ act_w,
                                             const float* __restrict__ act_b, float* __restrict__ h,
                                             float* __restrict__ hout, float* __restrict__ cum,
                                             float* __restrict__ halt) {
    int row = blockIdx.x; size_t base = (size_t)row * cD;
    int tid = threadIdx.x;
    float ss = 0.f;
#pragma unroll
    for (int i = 0; i < 4; i++) {
        int c = tid + i * 256;
        ss += hnew[base + c] * act_w[c];
    }
    __shared__ float red[256]; __shared__ float wsh;
    red[tid] = ss; __syncthreads();
    for (int s = 128; s > 0; s >>= 1) { if (tid < s) red[tid] += red[tid + s]; __syncthreads(); }
    if (tid == 0) {
        float z = red[0] + act_b[0];
        float p = 1.f / (1.f + expf(-z));
        float cm = cum[row]; float hl = halt[row];
        float p_eff = (hl > 0.5f) ? 0.f : p;
        float ncum = cm + p_eff;
        bool newly = (hl < 0.5f) && (ncum >= 0.99f);
        float w = newly ? (1.f - cm) : p_eff;
        cum[row] = ncum;
        if (newly) halt[row] = 1.f;
        wsh = w;
    }
    __syncthreads();
    float w = wsh;
#pragma unroll
    for (int i = 0; i < 4; i++) {
        int c = tid + i * 256;
        float v = hnew[base + c];
        hout[base + c] += w * v;
        h[base + c] = v;
    }
}

// ---------------- host ----------------
static void gemmB(const __nv_bfloat16* Ah, const __nv_bfloat16* Al,
                  const __nv_bfloat16* Bh, const __nv_bfloat16* Bl,
                  float* C, const float* Ci, int M, int N, int K, float scale, int epi) {
    dim3 g(N / GTN, M / GTM);
    gemm_bf16<<<g, 256, GEMM_SMEM>>>(Ah, Al, Bh, Bl, C, Ci, M, N, K, scale, epi);
}

extern "C" void kernel_launch(void* const* d_in, const int* in_sizes, int n_in,
                              void* d_out, int out_size) {
    const float* in_h  = (const float*)d_in[0];
    const float* in_e  = (const float*)d_in[1];
    const float* nw    = (const float*)d_in[2];
    const float* onw   = (const float*)d_in[3];
    const float* Wq    = (const float*)d_in[4];
    const float* Wk    = (const float*)d_in[5];
    const float* Wv    = (const float*)d_in[6];
    const float* Wgk   = (const float*)d_in[7];
    const float* Wg    = (const float*)d_in[8];
    const float* Wo    = (const float*)d_in[9];
    const float* loraA = (const float*)d_in[10];
    const float* loraB = (const float*)d_in[11];
    const float* injA  = (const float*)d_in[12];
    const float* injB  = (const float*)d_in[13];
    const float* act_w = (const float*)d_in[14];
    const float* act_b = (const float*)d_in[15];
    const float* ltab  = (const float*)d_in[16];
    float* out = (float*)d_out;

    float *p_h, *p_q, *p_k, *p_la, *p_v, *p_gate, *p_o, *p_kv, *p_S, *p_bdec,
          *p_gla, *p_lora, *p_hnew, *p_hout, *p_cum, *p_halt, *p_einj;
    cudaGetSymbolAddress((void**)&p_h, g_h);
    cudaGetSymbolAddress((void**)&p_q, g_q);
    cudaGetSymbolAddress((void**)&p_k, g_k);
    cudaGetSymbolAddress((void**)&p_la, g_la);
    cudaGetSymbolAddress((void**)&p_v, g_v);
    cudaGetSymbolAddress((void**)&p_gate, g_gate);
    cudaGetSymbolAddress((void**)&p_o, g_o);
    cudaGetSymbolAddress((void**)&p_kv, g_kv);
    cudaGetSymbolAddress((void**)&p_S, g_S);
    cudaGetSymbolAddress((void**)&p_bdec, g_bdec);
    cudaGetSymbolAddress((void**)&p_gla, g_gla);
    cudaGetSymbolAddress((void**)&p_lora, g_lora);
    cudaGetSymbolAddress((void**)&p_hnew, g_hnew);
    cudaGetSymbolAddress((void**)&p_hout, g_hout);
    cudaGetSymbolAddress((void**)&p_cum, g_cum);
    cudaGetSymbolAddress((void**)&p_halt, g_halt);
    cudaGetSymbolAddress((void**)&p_einj, g_einj);

    __nv_bfloat16 *wqh, *wql, *wkh, *wkl, *wgkh, *wgkl, *wvh, *wvl, *wgh, *wgl,
                  *woh, *wol, *iah, *ial, *ibh, *ibl, *eh, *el, *xh, *xl, *hh, *hl, *oh, *ol;
    cudaGetSymbolAddress((void**)&wqh, g_wqh);  cudaGetSymbolAddress((void**)&wql, g_wql);
    cudaGetSymbolAddress((void**)&wkh, g_wkh);  cudaGetSymbolAddress((void**)&wkl, g_wkl);
    cudaGetSymbolAddress((void**)&wgkh, g_wgkh); cudaGetSymbolAddress((void**)&wgkl, g_wgkl);
    cudaGetSymbolAddress((void**)&wvh, g_wvh);  cudaGetSymbolAddress((void**)&wvl, g_wvl);
    cudaGetSymbolAddress((void**)&wgh, g_wgh);  cudaGetSymbolAddress((void**)&wgl, g_wgl);
    cudaGetSymbolAddress((void**)&woh, g_woh);  cudaGetSymbolAddress((void**)&wol, g_wol);
    cudaGetSymbolAddress((void**)&iah, g_iah);  cudaGetSymbolAddress((void**)&ial, g_ial);
    cudaGetSymbolAddress((void**)&ibh, g_ibh);  cudaGetSymbolAddress((void**)&ibl, g_ibl);
    cudaGetSymbolAddress((void**)&eh, g_eh);    cudaGetSymbolAddress((void**)&el, g_el);
    cudaGetSymbolAddress((void**)&xh, g_xh);    cudaGetSymbolAddress((void**)&xl, g_xl);
    cudaGetSymbolAddress((void**)&hh, g_hh2);   cudaGetSymbolAddress((void**)&hl, g_hl2);
    cudaGetSymbolAddress((void**)&oh, g_oh);    cudaGetSymbolAddress((void**)&ol, g_ol);

    cudaFuncSetAttribute(k_chunk, cudaFuncAttributeMaxDynamicSharedMemorySize, SMEM_CHUNK);
    cudaFuncSetAttribute(gemm_bf16, cudaFuncAttributeMaxDynamicSharedMemorySize, GEMM_SMEM);

    const int nBig = cM * cD / 256;
    k_copy<<<nBig, 256>>>(p_h, in_h);
    k_zero<<<nBig, 256>>>(p_hout);
    k_zero_state<<<cM / 256, 256>>>(p_cum, p_halt);

    dim3 tb(32, 8);
    k_wconvT<<<dim3(cDK / 32, cD / 32), tb>>>(Wq,  wqh,  wql,  cD, cDK);
    k_wconvT<<<dim3(cDK / 32, cD / 32), tb>>>(Wk,  wkh,  wkl,  cD, cDK);
    k_wconvT<<<dim3(cDK / 32, cD / 32), tb>>>(Wgk, wgkh, wgkl, cD, cDK);
    k_wconvT<<<dim3(cDV / 32, cD / 32), tb>>>(Wv,  wvh,  wvl,  cD, cDV);
    k_wconvT<<<dim3(cDV / 32, cD / 32), tb>>>(Wg,  wgh,  wgl,  cD, cDV);
    k_wconvT<<<dim3(cD / 32, cDV / 32), tb>>>(Wo,  woh,  wol,  cDV, cD);
    k_split<<<cD * cD / 1024, 256>>>(injA, iah, ial);
    k_split<<<cD * cD / 1024, 256>>>(injB, ibh, ibl);
    k_split<<<cM * cD / 1024, 256>>>(in_e, eh, el);

    // loop-invariant: einj = e @ injB^T
    gemmB(eh, el, ibh, ibl, p_einj, nullptr, cM, cD, cD, 0.f, 0);

    const float qscale = 0.08838834764831845f;

    for (int t = 0; t < cNL; t++) {
        k_prep<<<cM, 256>>>(p_h, in_e, nw, ltab + t * cLOOPD, xh, xl, hh, hl);

        gemmB(xh, xl, wqh,  wql,  p_q,    nullptr, cM, cDK, cD, qscale, 1);
        gemmB(xh, xl, wkh,  wkl,  p_k,    nullptr, cM, cDK, cD, 0.f, 0);
        gemmB(xh, xl, wgkh, wgkl, p_la,   nullptr, cM, cDK, cD, 0.f, 2);
        gemmB(xh, xl, wvh,  wvl,  p_v,    nullptr, cM, cDV, cD, 0.f, 0);
        gemmB(xh, xl, wgh,  wgl,  p_gate, nullptr, cM, cDV, cD, 0.f, 3);

        k_chunk<<<cNC * cBH, 256, SMEM_CHUNK>>>(p_q, p_k, p_la, p_v, p_o, p_kv, p_bdec);
        k_state<<<cBH * 8, 256>>>(p_kv, p_bdec, p_S);
        // inter-chunk + gate fused, emits bf16 hi/lo o directly
        k_inter<<<cNC * cBH, 256>>>(p_q, p_S, p_o, p_gate, oh, ol);

        // pure g = (o*silu(gate)) @ Wo^T
        gemmB(oh, ol, woh, wol, p_gla, nullptr, cM, cD, cDV, 0.f, 0);

        k_lora_down<<<cM / 8, 256>>>(p_gla, loraA + (size_t)t * cD * cRANK, p_lora);
        k_lora_up<<<nBig, 256>>>(p_lora, loraB + (size_t)t * cRANK * cD, p_einj, p_gla);

        gemmB(hh, hl, iah, ial, p_hnew, p_gla, cM, cD, cD, 0.f, 0);

        k_act<<<cM, 256>>>(p_hnew, act_w, act_b, p_h, p_hout, p_cum, p_halt);
    }
    k_rmsnorm<<<cM, 256>>>(p_hout, onw, out);
}